// round 6
// baseline (speedup 1.0000x reference)
#include <cuda_runtime.h>
#include <cuda_bf16.h>

// Problem constants
#define BB   512    // batch
#define TT   256    // time steps
#define II   256    // input dim
#define HH   256    // hidden dim

// Tiling
#define NBLK 128    // 8 batch-tiles x 16 hidden-tiles (must all be co-resident: 128 <= 148 SMs)
#define BTIL 64     // batch rows per block
#define HTIL 16     // hidden units per block (x4 gates = 64 gate rows)
#define LD   68     // smem row stride (floats), padded

// Scratch (allocation-free rule: __device__ globals)
__device__ float        g_hs[(size_t)BB * TT * HH];   // h at every step  (128 MB)
__device__ float        g_cfin[(size_t)BB * HH];      // final cell state
__device__ unsigned int g_bar;                        // grid barrier counter

__global__ void init_kernel() { g_bar = 0u; }

__device__ __forceinline__ float sigf(float v) { return 1.0f / (1.0f + __expf(-v)); }

#define PACK2(D, LO, HI)  asm("mov.b64 %0,{%1,%2};" : "=l"(D) : "f"(LO), "f"(HI))
#define UNPACK2(LO, HI, S) asm("mov.b64 {%0,%1},%2;" : "=f"(LO), "=f"(HI) : "l"(S))
#define FMA2(ACC, AA, BV)  asm("fma.rn.f32x2 %0,%1,%2,%0;" : "+l"(ACC) : "l"(AA), "l"(BV))

// Persistent recurrent kernel.
// Grid: 128 blocks. blockIdx.x = hb*8 + bb ; bb in [0,8) batch tile, hb in [0,16) hidden tile.
// Each block: keeps W slice [64 gate rows x 512 K] in smem for all T steps,
// owns c for its (64 batch x 16 hidden) slice in registers, exchanges h via g_hs
// with a monotonic atomic grid barrier per step.
__global__ void __launch_bounds__(256, 1) lstm_rec(
    const float* __restrict__ x,        // [B,T,I]
    const int*   __restrict__ is_init,  // [B,T]
    const float* __restrict__ hx,       // [B,1,H]
    const float* __restrict__ cx,       // [B,1,H]
    const float* __restrict__ Wih,      // [4H,I]
    const float* __restrict__ Whh,      // [4H,H]
    const float* __restrict__ bih,      // [4H]
    const float* __restrict__ bhh)      // [4H]
{
    extern __shared__ float sm[];
    float* Ws   = sm;                 // [512][LD]  weight slice, W[k][r]
    float* As   = Ws + 512 * LD;      // [64][LD]   A chunk, A[kk][row]
    float* Gs   = As + 64 * LD;       // [64][LD]   gates, G[row][r]
    float* bias = Gs + 64 * LD;       // [64]
    float* rset = bias + 64;          // [64]

    const int tid = threadIdx.x;
    const int bb  = blockIdx.x & 7;
    const int hb  = blockIdx.x >> 3;
    const int b0  = bb * BTIL;
    const int h0  = hb * HTIL;

    // ---- one-time: load W slice (rows: r = g*16 + j -> global row g*256 + h0 + j) ----
    for (int idx = tid; idx < 64 * 512; idx += 256) {
        int r  = idx >> 9;          // 0..63
        int k  = idx & 511;         // 0..511 (coalesced)
        int gr = (r >> 4) * HH + h0 + (r & 15);
        float w = (k < 256) ? Wih[gr * II + k] : Whh[gr * HH + (k - 256)];
        Ws[k * LD + r] = w;
    }
    if (tid < 64) {
        int gr = (tid >> 4) * HH + h0 + (tid & 15);
        bias[tid] = bih[gr] + bhh[gr];
    }

    const int tx  = tid & 15, ty = tid >> 4;
    const int tx4 = tx * 4,  ty4 = ty * 4;
    const int rloc = tid >> 2;           // batch row (0..63) for loads & c-update
    const int kq   = (tid & 3) * 4;      // k/j sub-offset

    // ---- cell state registers for this thread's 4 elements: (b0+rloc, h0+kq+m) ----
    float c[4];
    {
        float4 cv = *reinterpret_cast<const float4*>(cx + (size_t)(b0 + rloc) * HH + h0 + kq);
        c[0] = cv.x; c[1] = cv.y; c[2] = cv.z; c[3] = cv.w;
    }

    for (int t = 0; t < TT; ++t) {
        if (tid < 64) rset[tid] = 1.0f - (float)is_init[(size_t)(b0 + tid) * TT + t];

        unsigned long long acc[4][2];
        #pragma unroll
        for (int i = 0; i < 4; ++i) { acc[i][0] = 0ull; acc[i][1] = 0ull; }

        // ---- GEMM: gates[64 x 64] = A[64 x 512] * Wslice^T, K chunks of 64 ----
        for (int ch = 0; ch < 8; ++ch) {
            __syncthreads();
            if (ch < 4) {  // x part, k in [0,256)
                const float* src = x + ((size_t)(b0 + rloc) * TT + t) * II + ch * 64;
                #pragma unroll
                for (int q = 0; q < 4; ++q) {
                    int kk = kq + q * 16;
                    float4 v = *reinterpret_cast<const float4*>(src + kk);
                    As[(kk + 0) * LD + rloc] = v.x;
                    As[(kk + 1) * LD + rloc] = v.y;
                    As[(kk + 2) * LD + rloc] = v.z;
                    As[(kk + 3) * LD + rloc] = v.w;
                }
            } else {       // h part, k in [256,512): h_prev * reset
                float rs = rset[rloc];
                const float* hsrc = (t == 0)
                    ? (hx + (size_t)(b0 + rloc) * HH)
                    : (g_hs + ((size_t)(b0 + rloc) * TT + (t - 1)) * HH);
                int khb = (ch - 4) * 64;
                #pragma unroll
                for (int q = 0; q < 4; ++q) {
                    int kk = kq + q * 16;
                    float4 v = *reinterpret_cast<const float4*>(hsrc + khb + kk);
                    As[(kk + 0) * LD + rloc] = v.x * rs;
                    As[(kk + 1) * LD + rloc] = v.y * rs;
                    As[(kk + 2) * LD + rloc] = v.z * rs;
                    As[(kk + 3) * LD + rloc] = v.w * rs;
                }
            }
            __syncthreads();

            const float* Wc = Ws + ch * 64 * LD;
            #pragma unroll 16
            for (int kk = 0; kk < 64; ++kk) {
                float4 av = *reinterpret_cast<const float4*>(As + kk * LD + ty4);
                float4 bv = *reinterpret_cast<const float4*>(Wc + kk * LD + tx4);
                unsigned long long b01, b23, aa;
                PACK2(b01, bv.x, bv.y);
                PACK2(b23, bv.z, bv.w);
                PACK2(aa, av.x, av.x); FMA2(acc[0][0], aa, b01); FMA2(acc[0][1], aa, b23);
                PACK2(aa, av.y, av.y); FMA2(acc[1][0], aa, b01); FMA2(acc[1][1], aa, b23);
                PACK2(aa, av.z, av.z); FMA2(acc[2][0], aa, b01); FMA2(acc[2][1], aa, b23);
                PACK2(aa, av.w, av.w); FMA2(acc[3][0], aa, b01); FMA2(acc[3][1], aa, b23);
            }
        }

        // ---- scatter gates to smem so each thread can gather i/f/g/o ----
        #pragma unroll
        for (int i = 0; i < 4; ++i) {
            float g0, g1, g2, g3;
            UNPACK2(g0, g1, acc[i][0]);
            UNPACK2(g2, g3, acc[i][1]);
            *reinterpret_cast<float4*>(Gs + (ty4 + i) * LD + tx4) = make_float4(g0, g1, g2, g3);
        }
        __syncthreads();

        // ---- elementwise: c/h update for this thread's 4 (b,h) elements ----
        {
            float rs = rset[rloc];
            float hv[4];
            #pragma unroll
            for (int m = 0; m < 4; ++m) {
                int j = kq + m;
                float gi = sigf (Gs[rloc * LD + j]      + bias[j]);
                float gf = sigf (Gs[rloc * LD + 16 + j] + bias[16 + j]);
                float gg = tanhf(Gs[rloc * LD + 32 + j] + bias[32 + j]);
                float go = sigf (Gs[rloc * LD + 48 + j] + bias[48 + j]);
                float cc = c[m] * rs;
                cc = gf * cc + gi * gg;
                c[m] = cc;
                hv[m] = go * tanhf(cc);
            }
            *reinterpret_cast<float4*>(
                g_hs + ((size_t)(b0 + rloc) * TT + t) * HH + h0 + kq)
                = make_float4(hv[0], hv[1], hv[2], hv[3]);
        }

        // ---- grid barrier (monotonic counter; g_bar zeroed by init_kernel) ----
        __threadfence();            // release h writes (all threads)
        __syncthreads();
        if (tid == 0) {
            atomicAdd(&g_bar, 1u);
            unsigned int target = (unsigned int)(t + 1) * (unsigned int)NBLK;
            while (*((volatile unsigned int*)&g_bar) < target) { }
        }
        __syncthreads();
        __threadfence();            // acquire other blocks' h writes
    }

    // final cell state
    *reinterpret_cast<float4*>(g_cfin + (size_t)(b0 + rloc) * HH + h0 + kq)
        = make_float4(c[0], c[1], c[2], c[3]);
}

// Epilogue: LayerNorm(h) + x skip, plus broadcast hT and cT.
// One warp per (b,t) row of 256; 8 warps/block; grid = B*T/8.
__global__ void __launch_bounds__(256) lstm_epi(
    const float* __restrict__ x,
    const float* __restrict__ lnw,
    const float* __restrict__ lnb,
    float* __restrict__ out)
{
    const int warp = threadIdx.x >> 5;
    const int lane = threadIdx.x & 31;
    const size_t row = (size_t)blockIdx.x * 8 + warp;   // 0..B*T-1
    const int b = (int)(row >> 8);                       // T = 256

    const float* hrow = g_hs + row * HH;
    float4 a  = *reinterpret_cast<const float4*>(hrow + lane * 4);
    float4 bq = *reinterpret_cast<const float4*>(hrow + 128 + lane * 4);

    float s  = a.x + a.y + a.z + a.w + bq.x + bq.y + bq.z + bq.w;
    float ss = a.x*a.x + a.y*a.y + a.z*a.z + a.w*a.w
             + bq.x*bq.x + bq.y*bq.y + bq.z*bq.z + bq.w*bq.w;
    #pragma unroll
    for (int o = 16; o > 0; o >>= 1) {
        s  += __shfl_xor_sync(0xffffffffu, s,  o);
        ss += __shfl_xor_sync(0xffffffffu, ss, o);
    }
    float mu  = s * (1.0f / 256.0f);
    float var = ss * (1.0f / 256.0f) - mu * mu;
    float inv = rsqrtf(var + 1e-5f);

    const size_t N1 = (size_t)BB * TT * HH;
    const float* hT = g_hs + ((size_t)b * TT + (TT - 1)) * HH;
    const float* cT = g_cfin + (size_t)b * HH;

    #pragma unroll
    for (int half = 0; half < 2; ++half) {
        int i0 = half * 128 + lane * 4;
        float4 hv = half ? bq : a;
        float4 xv = *reinterpret_cast<const float4*>(x   + row * II + i0);
        float4 wv = *reinterpret_cast<const float4*>(lnw + i0);
        float4 bv = *reinterpret_cast<const float4*>(lnb + i0);
        float4 o1;
        o1.x = xv.x + (hv.x - mu) * inv * wv.x + bv.x;
        o1.y = xv.y + (hv.y - mu) * inv * wv.y + bv.y;
        o1.z = xv.z + (hv.z - mu) * inv * wv.z + bv.z;
        o1.w = xv.w + (hv.w - mu) * inv * wv.w + bv.w;
        *reinterpret_cast<float4*>(out + row * HH + i0) = o1;

        *reinterpret_cast<float4*>(out + N1 + row * HH + i0)
            = *reinterpret_cast<const float4*>(hT + i0);
        *reinterpret_cast<float4*>(out + 2 * N1 + row * HH + i0)
            = *reinterpret_cast<const float4*>(cT + i0);
    }
}

extern "C" void kernel_launch(void* const* d_in, const int* in_sizes, int n_in,
                              void* d_out, int out_size) {
    const float* x       = (const float*)d_in[0];
    const int*   is_init = (const int*)  d_in[1];
    const float* hx      = (const float*)d_in[2];
    const float* cx      = (const float*)d_in[3];
    const float* Wih     = (const float*)d_in[4];
    const float* Whh     = (const float*)d_in[5];
    const float* bih     = (const float*)d_in[6];
    const float* bhh     = (const float*)d_in[7];
    const float* lnw     = (const float*)d_in[8];
    const float* lnb     = (const float*)d_in[9];
    float* out = (float*)d_out;

    const size_t smem = (size_t)(512 * LD + 64 * LD + 64 * LD + 128) * sizeof(float);
    cudaFuncSetAttribute(lstm_rec, cudaFuncAttributeMaxDynamicSharedMemorySize, (int)smem);

    init_kernel<<<1, 1>>>();
    lstm_rec<<<NBLK, 256, smem>>>(x, is_init, hx, cx, Wih, Whh, bih, bhh);
    lstm_epi<<<(BB * TT) / 8, 256>>>(x, lnw, lnb, out);
}

// round 8
// speedup vs baseline: 2.1323x; 2.1323x over previous
#include <cuda_runtime.h>
#include <cuda_fp16.h>
#include <cstdint>

#define BB 512
#define TT 256
#define II 256
#define HH 256
#define NBLK 128
#define LDA 520            // fp16 row stride for A/B smem (pad 8 -> conflict-free ldmatrix)
#define LDG_ 68            // fp32 row stride for gate smem

// smem byte offsets
#define SM_A    0
#define SM_B    66560      // 64*520*2
#define SM_G    133120
#define SM_BIAS 150528
#define SM_RSET 150784
#define SM_TOT  151040

__device__ float        g_hs[(size_t)BB * TT * HH];
__device__ float        g_cfin[(size_t)BB * HH];
__device__ unsigned int g_bar;
__global__ void init_kernel() { g_bar = 0u; }

static __device__ __forceinline__ uint32_t smem_u32(const void* p) {
    uint32_t a;
    asm("{ .reg .u64 t; cvta.to.shared.u64 t, %1; cvt.u32.u64 %0, t; }" : "=r"(a) : "l"(p));
    return a;
}
static __device__ __forceinline__ void ldsm4(uint32_t (&r)[4], uint32_t addr) {
    asm volatile("ldmatrix.sync.aligned.m8n8.x4.shared.b16 {%0,%1,%2,%3}, [%4];"
                 : "=r"(r[0]), "=r"(r[1]), "=r"(r[2]), "=r"(r[3]) : "r"(addr));
}
static __device__ __forceinline__ void hmma(float (&d)[4], const uint32_t (&a)[4],
                                            uint32_t b0, uint32_t b1) {
    asm volatile("mma.sync.aligned.m16n8k16.row.col.f32.f16.f16.f32 "
                 "{%0,%1,%2,%3}, {%4,%5,%6,%7}, {%8,%9}, {%0,%1,%2,%3};"
                 : "+f"(d[0]), "+f"(d[1]), "+f"(d[2]), "+f"(d[3])
                 : "r"(a[0]), "r"(a[1]), "r"(a[2]), "r"(a[3]), "r"(b0), "r"(b1));
}
static __device__ __forceinline__ float sigf(float v) { return 1.0f / (1.0f + __expf(-v)); }

// Convert float4 -> 2x half2 and store 8 bytes to smem
static __device__ __forceinline__ void st_h4(char* dst, float4 v) {
    __half2 h01 = __floats2half2_rn(v.x, v.y);
    __half2 h23 = __floats2half2_rn(v.z, v.w);
    uint32_t u0 = *(uint32_t*)&h01, u1 = *(uint32_t*)&h23;
    asm volatile("st.shared.v2.b32 [%0], {%1,%2};" :: "r"(smem_u32(dst)), "r"(u0), "r"(u1) : "memory");
}

__global__ void __launch_bounds__(256, 1) lstm_rec(
    const float* __restrict__ x,  const int*   __restrict__ is_init,
    const float* __restrict__ hx, const float* __restrict__ cx,
    const float* __restrict__ Wih, const float* __restrict__ Whh,
    const float* __restrict__ bih, const float* __restrict__ bhh)
{
    extern __shared__ char smc[];
    __half* As = (__half*)(smc + SM_A);
    __half* Bs = (__half*)(smc + SM_B);
    float*  Gs = (float*)(smc + SM_G);
    float*  bias = (float*)(smc + SM_BIAS);
    float*  rset = (float*)(smc + SM_RSET);

    const int tid = threadIdx.x, wid = tid >> 5, lane = tid & 31;
    const int bb = blockIdx.x & 7, hb = blockIdx.x >> 3;
    const int b0 = bb * 64, h0 = hb * 16;

    // ---- one-time: W slice -> Bs[n][k] fp16 (n = gate*16 + j, k = 0..511) ----
    for (int idx = tid; idx < 64 * 512; idx += 256) {
        int n = idx >> 9, k = idx & 511;
        int grow = (n >> 4) * HH + h0 + (n & 15);
        float w = (k < 256) ? Wih[grow * II + k] : Whh[grow * HH + (k - 256)];
        Bs[n * LDA + k] = __float2half_rn(w);
    }
    if (tid < 64) {
        int grow = (tid >> 4) * HH + h0 + (tid & 15);
        bias[tid] = bih[grow] + bhh[grow];
    }

    // MMA warp tiling: wm = wid&3 -> m0, wn = wid>>2 -> n0
    const int m0 = (wid & 3) * 16, n0 = (wid >> 2) * 32;
    const uint32_t sa = smem_u32(As), sbm = smem_u32(Bs);
    // ldmatrix per-lane byte offsets
    const uint32_t a_off = ((m0 + (lane & 7) + ((lane >> 3) & 1) * 8) * LDA + (lane >> 4) * 8) * 2;
    const uint32_t b_row = (lane & 7) + (lane >> 4) * 8;
    const uint32_t b_col = ((lane >> 3) & 1) * 8;
    const uint32_t b_off0 = ((n0 +      b_row) * LDA + b_col) * 2;
    const uint32_t b_off1 = ((n0 + 16 + b_row) * LDA + b_col) * 2;

    // staging: thread -> row = tid&63, quarter q = tid>>6 (uniform per warp)
    const int srow = tid & 63, q = tid >> 6;
    char* sdst = (char*)(As + srow * LDA + q * 128);

    // elementwise ownership (R4 mapping)
    const int rloc = tid >> 2, kq = (tid & 3) * 4;
    float c[4];
    {
        float4 cv = *(const float4*)(cx + (size_t)(b0 + rloc) * HH + h0 + kq);
        c[0] = cv.x; c[1] = cv.y; c[2] = cv.z; c[3] = cv.w;
    }

    for (int t = 0; t < TT; ++t) {
        if (tid < 64) rset[tid] = 1.0f - (float)is_init[(size_t)(b0 + tid) * TT + t];
        __syncthreads();

        // ---- stage A[64 x 512] fp16: k<256 from x, k>=256 from h_prev * reset ----
        if (q < 2) {
            const float* sp = x + ((size_t)(b0 + srow) * TT + t) * II + q * 128;
            #pragma unroll 8
            for (int j = 0; j < 32; ++j)
                st_h4(sdst + j * 8, *(const float4*)(sp + j * 4));
        } else {
            float rs = rset[srow];
            const float* sp = (t == 0)
                ? hx + (size_t)(b0 + srow) * HH + (q - 2) * 128
                : g_hs + ((size_t)(b0 + srow) * TT + (t - 1)) * HH + (q - 2) * 128;
            #pragma unroll 8
            for (int j = 0; j < 32; ++j) {
                float4 v = *(const float4*)(sp + j * 4);
                v.x *= rs; v.y *= rs; v.z *= rs; v.w *= rs;
                st_h4(sdst + j * 8, v);
            }
        }
        __syncthreads();

        // ---- GEMM: 32 k-steps of m16n8k16; warp computes m16 x n32 ----
        float acc[4][4];
        #pragma unroll
        for (int i = 0; i < 4; ++i)
            { acc[i][0] = 0.f; acc[i][1] = 0.f; acc[i][2] = 0.f; acc[i][3] = 0.f; }

        #pragma unroll 4
        for (int ks = 0; ks < 32; ++ks) {
            uint32_t kb = ks * 32;   // k offset in bytes (16 fp16)
            uint32_t a[4], b0r[4], b1r[4];
            ldsm4(a,   sa  + a_off  + kb);
            ldsm4(b0r, sbm + b_off0 + kb);
            ldsm4(b1r, sbm + b_off1 + kb);
            hmma(acc[0], a, b0r[0], b0r[1]);
            hmma(acc[1], a, b0r[2], b0r[3]);
            hmma(acc[2], a, b1r[0], b1r[1]);
            hmma(acc[3], a, b1r[2], b1r[3]);
        }

        // ---- store gates to Gs ----
        {
            int gr = m0 + lane / 4;
            int gc = n0 + (lane & 3) * 2;
            #pragma unroll
            for (int nt = 0; nt < 4; ++nt) {
                int col = gc + nt * 8;
                *(float2*)(Gs + gr * LDG_ + col)       = make_float2(acc[nt][0], acc[nt][1]);
                *(float2*)(Gs + (gr + 8) * LDG_ + col) = make_float2(acc[nt][2], acc[nt][3]);
            }
        }
        __syncthreads();

        // ---- elementwise c/h update (R4 proven) ----
        {
            float rs = rset[rloc];
            float hv[4];
            #pragma unroll
            for (int m = 0; m < 4; ++m) {
                int j = kq + m;
                float gi = sigf (Gs[rloc * LDG_ + j]      + bias[j]);
                float gf = sigf (Gs[rloc * LDG_ + 16 + j] + bias[16 + j]);
                float gg = tanhf(Gs[rloc * LDG_ + 32 + j] + bias[32 + j]);
                float go = sigf (Gs[rloc * LDG_ + 48 + j] + bias[48 + j]);
                float cc = c[m] * rs;
                cc = gf * cc + gi * gg;
                c[m] = cc;
                hv[m] = go * tanhf(cc);
            }
            *(float4*)(g_hs + ((size_t)(b0 + rloc) * TT + t) * HH + h0 + kq)
                = make_float4(hv[0], hv[1], hv[2], hv[3]);
        }

        // ---- grid barrier ----
        __threadfence();
        __syncthreads();
        if (tid == 0) {
            atomicAdd(&g_bar, 1u);
            unsigned int target = (unsigned int)(t + 1) * (unsigned int)NBLK;
            while (*((volatile unsigned int*)&g_bar) < target) { }
        }
        __syncthreads();
        __threadfence();
    }

    *(float4*)(g_cfin + (size_t)(b0 + rloc) * HH + h0 + kq)
        = make_float4(c[0], c[1], c[2], c[3]);
}

__global__ void __launch_bounds__(256) lstm_epi(
    const float* __restrict__ x, const float* __restrict__ lnw,
    const float* __restrict__ lnb, float* __restrict__ out)
{
    const int warp = threadIdx.x >> 5, lane = threadIdx.x & 31;
    const size_t row = (size_t)blockIdx.x * 8 + warp;
    const int b = (int)(row >> 8);

    const float* hrow = g_hs + row * HH;
    float4 a  = *(const float4*)(hrow + lane * 4);
    float4 bq = *(const float4*)(hrow + 128 + lane * 4);

    float s1 = a.x + a.y + a.z + a.w + bq.x + bq.y + bq.z + bq.w;
    float s2 = a.x*a.x + a.y*a.y + a.z*a.z + a.w*a.w
             + bq.x*bq.x + bq.y*bq.y + bq.z*bq.z + bq.w*bq.w;
    #pragma unroll
    for (int o = 16; o > 0; o >>= 1) {
        s1 += __shfl_xor_sync(0xffffffffu, s1, o);
        s2 += __shfl_xor_sync(0xffffffffu, s2, o);
    }
    float mu  = s1 * (1.0f / 256.0f);
    float var = s2 * (1.0f / 256.0f) - mu * mu;
    float inv = rsqrtf(var + 1e-5f);

    const size_t N1 = (size_t)BB * TT * HH;
    const float* hT = g_hs + ((size_t)b * TT + (TT - 1)) * HH;
    const float* cT = g_cfin + (size_t)b * HH;

    #pragma unroll
    for (int half = 0; half < 2; ++half) {
        int i0 = half * 128 + lane * 4;
        float4 hv = half ? bq : a;
        float4 xv = *(const float4*)(x   + row * II + i0);
        float4 wv = *(const float4*)(lnw + i0);
        float4 bv = *(const float4*)(lnb + i0);
        float4 o1;
        o1.x = xv.x + (hv.x - mu) * inv * wv.x + bv.x;
        o1.y = xv.y + (hv.y - mu) * inv * wv.y + bv.y;
        o1.z = xv.z + (hv.z - mu) * inv * wv.z + bv.z;
        o1.w = xv.w + (hv.w - mu) * inv * wv.w + bv.w;
        *(float4*)(out + row * HH + i0) = o1;
        *(float4*)(out + N1 + row * HH + i0)     = *(const float4*)(hT + i0);
        *(float4*)(out + 2 * N1 + row * HH + i0) = *(const float4*)(cT + i0);
    }
}

extern "C" void kernel_launch(void* const* d_in, const int* in_sizes, int n_in,
                              void* d_out, int out_size) {
    const float* x   = (const float*)d_in[0];
    const int*   ini = (const int*)  d_in[1];
    const float* hx  = (const float*)d_in[2];
    const float* cx  = (const float*)d_in[3];
    const float* Wih = (const float*)d_in[4];
    const float* Whh = (const float*)d_in[5];
    const float* bih = (const float*)d_in[6];
    const float* bhh = (const float*)d_in[7];
    const float* lnw = (const float*)d_in[8];
    const float* lnb = (const float*)d_in[9];
    float* out = (float*)d_out;

    cudaFuncSetAttribute(lstm_rec, cudaFuncAttributeMaxDynamicSharedMemorySize, SM_TOT);
    init_kernel<<<1, 1>>>();
    lstm_rec<<<NBLK, 256, SM_TOT>>>(x, ini, hx, cx, Wih, Whh, bih, bhh);
    lstm_epi<<<(BB * TT) / 8, 256>>>(x, lnw, lnb, out);
}

// round 9
// speedup vs baseline: 2.8812x; 1.3512x over previous
#include <cuda_runtime.h>
#include <cuda_fp16.h>
#include <cstdint>

#define BB 512
#define TT 256
#define II 256
#define HH 256
#define NBLK 128
#define LDA 264           // halves per A/B smem row (256 + 8 pad)
#define LDG_ 68           // fp32 gate smem stride

// smem byte offsets
#define SM_W1   0                       // Wih slice 64x264 fp16
#define SM_W2   33792                   // Whh slice
#define SM_A0   67584
#define SM_A1   101376
#define SM_G    135168                  // 64x68 fp32
#define SM_BIAS 152576                  // 64 fp32
#define SM_MASK 152832                  // 64x8 u32 is_init bitmask
#define SM_TOT  154880

__device__ float        g_hs[(size_t)BB * TT * HH];     // fp32 h history (for LN)
__device__ __half       g_hs16[(size_t)BB * 512];       // fp16 h double buffer [B][2][H]
__device__ __half       g_x16[(size_t)BB * TT * II];    // fp16 x
__device__ float4       g_xp[(size_t)NBLK * TT * 1024]; // x_proj fragments (512MB)
__device__ float        g_cfin[(size_t)BB * HH];
__device__ unsigned int g_bars[8 * 32];

__global__ void init_kernel() {
    if (threadIdx.x < 8 * 32) g_bars[threadIdx.x] = 0u;
}

static __device__ __forceinline__ uint32_t smem_u32(const void* p) {
    uint32_t a;
    asm("{ .reg .u64 t; cvta.to.shared.u64 t, %1; cvt.u32.u64 %0, t; }" : "=r"(a) : "l"(p));
    return a;
}
static __device__ __forceinline__ void ldsm4(uint32_t (&r)[4], uint32_t addr) {
    asm volatile("ldmatrix.sync.aligned.m8n8.x4.shared.b16 {%0,%1,%2,%3}, [%4];"
                 : "=r"(r[0]), "=r"(r[1]), "=r"(r[2]), "=r"(r[3]) : "r"(addr));
}
static __device__ __forceinline__ void hmma(float (&d)[4], const uint32_t (&a)[4],
                                            uint32_t b0, uint32_t b1) {
    asm volatile("mma.sync.aligned.m16n8k16.row.col.f32.f16.f16.f32 "
                 "{%0,%1,%2,%3}, {%4,%5,%6,%7}, {%8,%9}, {%0,%1,%2,%3};"
                 : "+f"(d[0]), "+f"(d[1]), "+f"(d[2]), "+f"(d[3])
                 : "r"(a[0]), "r"(a[1]), "r"(a[2]), "r"(a[3]), "r"(b0), "r"(b1));
}
static __device__ __forceinline__ void cpa16(uint32_t dst, const void* src) {
    asm volatile("cp.async.ca.shared.global [%0], [%1], 16;" :: "r"(dst), "l"(src) : "memory");
}
#define CP_COMMIT() asm volatile("cp.async.commit_group;" ::: "memory")
#define CP_WAIT0()  asm volatile("cp.async.wait_group 0;" ::: "memory")

static __device__ __forceinline__ float sigf(float v) {
    return __fdividef(1.0f, 1.0f + __expf(-v));
}
static __device__ __forceinline__ float tanhfast(float v) {
    return 1.0f - __fdividef(2.0f, __expf(2.0f * v) + 1.0f);
}

// 16-kstep GEMM: acc (pre-initialized) += A[64x256](sa) * B[64x256](sb)^T
static __device__ __forceinline__ void gemm256(float (&acc)[4][4], uint32_t sa, uint32_t sb,
                                               uint32_t a_off, uint32_t b_off0, uint32_t b_off1) {
    #pragma unroll
    for (int ks = 0; ks < 16; ++ks) {
        uint32_t kb = ks * 32;
        uint32_t a[4], b0r[4], b1r[4];
        ldsm4(a,   sa + a_off  + kb);
        ldsm4(b0r, sb + b_off0 + kb);
        ldsm4(b1r, sb + b_off1 + kb);
        hmma(acc[0], a, b0r[0], b0r[1]);
        hmma(acc[1], a, b0r[2], b0r[3]);
        hmma(acc[2], a, b1r[0], b1r[1]);
        hmma(acc[3], a, b1r[2], b1r[3]);
    }
}

__global__ void __launch_bounds__(256) cvt_x(const float* __restrict__ x,
                                             const float* __restrict__ hx) {
    size_t gid = (size_t)blockIdx.x * blockDim.x + threadIdx.x;
    size_t stride = (size_t)gridDim.x * blockDim.x;
    size_t n4 = (size_t)BB * TT * II / 4;
    for (size_t i = gid; i < n4; i += stride) {
        float4 v = ((const float4*)x)[i];
        __half2 a = __floats2half2_rn(v.x, v.y), b = __floats2half2_rn(v.z, v.w);
        *(uint2*)&g_x16[i * 4] = make_uint2(*(uint32_t*)&a, *(uint32_t*)&b);
    }
    size_t nh = (size_t)BB * HH / 4;
    for (size_t i = gid; i < nh; i += stride) {
        float4 v = ((const float4*)hx)[i];
        int b = (int)(i >> 6), h4 = (int)(i & 63);
        __half2 a = __floats2half2_rn(v.x, v.y), c = __floats2half2_rn(v.z, v.w);
        *(uint2*)&g_hs16[(size_t)b * 512 + 256 + h4 * 4] = make_uint2(*(uint32_t*)&a, *(uint32_t*)&c);
    }
}

__global__ void __launch_bounds__(256, 1) lstm_rec(
    const int*   __restrict__ is_init,
    const float* __restrict__ cx,
    const float* __restrict__ Wih, const float* __restrict__ Whh,
    const float* __restrict__ bih, const float* __restrict__ bhh)
{
    extern __shared__ char smc[];
    float*    Gs   = (float*)(smc + SM_G);
    float*    bias = (float*)(smc + SM_BIAS);
    uint32_t* mask = (uint32_t*)(smc + SM_MASK);

    const int tid = threadIdx.x, wid = tid >> 5, lane = tid & 31;
    const int bb = blockIdx.x & 7, hb = blockIdx.x >> 3;
    const int b0 = bb * 64, h0 = hb * 16;

    // one-time: W slices fp16 [n][k], n = gate*16 + j
    for (int idx = tid; idx < 64 * 256; idx += 256) {
        int n = idx >> 8, k = idx & 255;
        int grow = (n >> 4) * HH + h0 + (n & 15);
        ((__half*)(smc + SM_W1))[n * LDA + k] = __float2half_rn(Wih[grow * II + k]);
        ((__half*)(smc + SM_W2))[n * LDA + k] = __float2half_rn(Whh[grow * HH + k]);
    }
    if (tid < 64) {
        int grow = (tid >> 4) * HH + h0 + (tid & 15);
        bias[tid] = bih[grow] + bhh[grow];
    }
    // is_init bitmask: mask[row][w], bit j = is_init[b0+row][w*32+j]
    {
        int row = tid >> 2, tseg = tid & 3;
        const int* ip = is_init + (size_t)(b0 + row) * TT + tseg * 64;
        #pragma unroll
        for (int w = 0; w < 2; ++w) {
            uint32_t m = 0;
            #pragma unroll 8
            for (int j = 0; j < 32; ++j) m |= (ip[w * 32 + j] ? 1u : 0u) << j;
            mask[row * 8 + tseg * 2 + w] = m;
        }
    }
    __syncthreads();

    const uint32_t sa0 = smem_u32(smc + SM_A0), sa1 = smem_u32(smc + SM_A1);
    const uint32_t sw1 = smem_u32(smc + SM_W1), sw2 = smem_u32(smc + SM_W2);

    const int m0 = (wid & 3) * 16, n0 = (wid >> 2) * 32;
    const uint32_t a_off = ((m0 + (lane & 7) + ((lane >> 3) & 1) * 8) * LDA + (lane >> 4) * 8) * 2;
    const uint32_t b_row = (lane & 7) + (lane >> 4) * 8;
    const uint32_t b_col = ((lane >> 3) & 1) * 8;
    const uint32_t b_off0 = ((n0 + b_row) * LDA + b_col) * 2;
    const uint32_t b_off1 = ((n0 + 16 + b_row) * LDA + b_col) * 2;

    // staging decomposition: row = tid>>2 (0..63), seg = tid&3 (128B each)
    const int srow = tid >> 2, seg = tid & 3;
    const uint32_t sdst_off = srow * 528 + seg * 128;

    const size_t xpbase = (((size_t)blockIdx.x * TT) * 8 + wid) * 128 + lane;

    // ================= phase 1: precompute x_proj =================
    {
        const __half* src0 = g_x16 + ((size_t)(b0 + srow) * TT + 0) * II + seg * 64;
        #pragma unroll
        for (int i = 0; i < 8; ++i) cpa16(sa0 + sdst_off + i * 16, src0 + i * 8);
        CP_COMMIT();
    }
    for (int t = 0; t < TT; ++t) {
        const uint32_t sa = (t & 1) ? sa1 : sa0;
        CP_WAIT0();
        __syncthreads();
        if (t + 1 < TT) {
            const uint32_t nb = (t & 1) ? sa0 : sa1;
            const __half* src = g_x16 + ((size_t)(b0 + srow) * TT + (t + 1)) * II + seg * 64;
            #pragma unroll
            for (int i = 0; i < 8; ++i) cpa16(nb + sdst_off + i * 16, src + i * 8);
            CP_COMMIT();
        }
        float acc[4][4];
        #pragma unroll
        for (int i = 0; i < 4; ++i) { acc[i][0]=0.f; acc[i][1]=0.f; acc[i][2]=0.f; acc[i][3]=0.f; }
        gemm256(acc, sa, sw1, a_off, b_off0, b_off1);
        float4* xp = g_xp + xpbase + (size_t)t * 8 * 128;
        #pragma unroll
        for (int nt = 0; nt < 4; ++nt)
            xp[nt * 32] = make_float4(acc[nt][0], acc[nt][1], acc[nt][2], acc[nt][3]);
        __syncthreads();
    }

    // ================= phase 2: recurrence =================
    const int rloc = tid >> 2, kq = (tid & 3) * 4;
    float c[4];
    {
        float4 cv = *(const float4*)(cx + (size_t)(b0 + rloc) * HH + h0 + kq);
        c[0] = cv.x; c[1] = cv.y; c[2] = cv.z; c[3] = cv.w;
    }
    unsigned int* barp = &g_bars[bb * 32];

    for (int t = 0; t < TT; ++t) {
        // acc init from x_proj fragments
        float acc[4][4];
        {
            const float4* xp = g_xp + xpbase + (size_t)t * 8 * 128;
            #pragma unroll
            for (int nt = 0; nt < 4; ++nt) {
                float4 v = xp[nt * 32];
                acc[nt][0] = v.x; acc[nt][1] = v.y; acc[nt][2] = v.z; acc[nt][3] = v.w;
            }
        }
        // stage h(t-1)*reset as fp16 (zero rows where is_init)
        {
            uint32_t bit = (mask[srow * 8 + (t >> 5)] >> (t & 31)) & 1u;
            if (!bit) {
                const __half* src = g_hs16 + (size_t)(b0 + srow) * 512 + ((t & 1) ^ 1) * 256 + seg * 64;
                #pragma unroll
                for (int i = 0; i < 8; ++i) cpa16(sa0 + sdst_off + i * 16, src + i * 8);
            } else {
                #pragma unroll
                for (int i = 0; i < 8; ++i)
                    *(float4*)(smc + SM_A0 + sdst_off + i * 16) = make_float4(0.f, 0.f, 0.f, 0.f);
            }
            CP_COMMIT();
            CP_WAIT0();
        }
        __syncthreads();

        gemm256(acc, sa0, sw2, a_off, b_off0, b_off1);

        {
            int gr = m0 + lane / 4;
            int gc = n0 + (lane & 3) * 2;
            #pragma unroll
            for (int nt = 0; nt < 4; ++nt) {
                int col = gc + nt * 8;
                *(float2*)(Gs + gr * LDG_ + col)       = make_float2(acc[nt][0], acc[nt][1]);
                *(float2*)(Gs + (gr + 8) * LDG_ + col) = make_float2(acc[nt][2], acc[nt][3]);
            }
        }
        __syncthreads();

        // elementwise
        {
            uint32_t bit = (mask[rloc * 8 + (t >> 5)] >> (t & 31)) & 1u;
            float rs = bit ? 0.0f : 1.0f;
            float hv[4];
            #pragma unroll
            for (int m = 0; m < 4; ++m) {
                int j = kq + m;
                float gi = sigf    (Gs[rloc * LDG_ + j]      + bias[j]);
                float gf = sigf    (Gs[rloc * LDG_ + 16 + j] + bias[16 + j]);
                float gg = tanhfast(Gs[rloc * LDG_ + 32 + j] + bias[32 + j]);
                float go = sigf    (Gs[rloc * LDG_ + 48 + j] + bias[48 + j]);
                float cc = gf * (c[m] * rs) + gi * gg;
                c[m] = cc;
                hv[m] = go * tanhfast(cc);
            }
            *(float4*)(g_hs + ((size_t)(b0 + rloc) * TT + t) * HH + h0 + kq)
                = make_float4(hv[0], hv[1], hv[2], hv[3]);
            __half2 p0 = __floats2half2_rn(hv[0], hv[1]);
            __half2 p1 = __floats2half2_rn(hv[2], hv[3]);
            *(uint2*)&g_hs16[(size_t)(b0 + rloc) * 512 + (t & 1) * 256 + h0 + kq]
                = make_uint2(*(uint32_t*)&p0, *(uint32_t*)&p1);
        }

        // per-batch-tile barrier (16 blocks)
        __threadfence();
        __syncthreads();
        if (tid == 0) {
            atomicAdd(barp, 1u);
            unsigned int target = (unsigned int)(t + 1) * 16u;
            while (*((volatile unsigned int*)barp) < target) { }
        }
        __syncthreads();
        __threadfence();
    }

    *(float4*)(g_cfin + (size_t)(b0 + rloc) * HH + h0 + kq)
        = make_float4(c[0], c[1], c[2], c[3]);
}

__global__ void __launch_bounds__(256) lstm_epi(
    const float* __restrict__ x, const float* __restrict__ lnw,
    const float* __restrict__ lnb, float* __restrict__ out)
{
    const int warp = threadIdx.x >> 5, lane = threadIdx.x & 31;
    const size_t row = (size_t)blockIdx.x * 8 + warp;
    const int b = (int)(row >> 8);

    const float* hrow = g_hs + row * HH;
    float4 a  = *(const float4*)(hrow + lane * 4);
    float4 bq = *(const float4*)(hrow + 128 + lane * 4);

    float s1 = a.x + a.y + a.z + a.w + bq.x + bq.y + bq.z + bq.w;
    float s2 = a.x*a.x + a.y*a.y + a.z*a.z + a.w*a.w
             + bq.x*bq.x + bq.y*bq.y + bq.z*bq.z + bq.w*bq.w;
    #pragma unroll
    for (int o = 16; o > 0; o >>= 1) {
        s1 += __shfl_xor_sync(0xffffffffu, s1, o);
        s2 += __shfl_xor_sync(0xffffffffu, s2, o);
    }
    float mu  = s1 * (1.0f / 256.0f);
    float var = s2 * (1.0f / 256.0f) - mu * mu;
    float inv = rsqrtf(var + 1e-5f);

    const size_t N1 = (size_t)BB * TT * HH;
    const float* hT = g_hs + ((size_t)b * TT + (TT - 1)) * HH;
    const float* cT = g_cfin + (size_t)b * HH;

    #pragma unroll
    for (int half = 0; half < 2; ++half) {
        int i0 = half * 128 + lane * 4;
        float4 hv = half ? bq : a;
        float4 xv = *(const float4*)(x   + row * II + i0);
        float4 wv = *(const float4*)(lnw + i0);
        float4 bv = *(const float4*)(lnb + i0);
        float4 o1;
        o1.x = xv.x + (hv.x - mu) * inv * wv.x + bv.x;
        o1.y = xv.y + (hv.y - mu) * inv * wv.y + bv.y;
        o1.z = xv.z + (hv.z - mu) * inv * wv.z + bv.z;
        o1.w = xv.w + (hv.w - mu) * inv * wv.w + bv.w;
        *(float4*)(out + row * HH + i0) = o1;
        *(float4*)(out + N1 + row * HH + i0)     = *(const float4*)(hT + i0);
        *(float4*)(out + 2 * N1 + row * HH + i0) = *(const float4*)(cT + i0);
    }
}

extern "C" void kernel_launch(void* const* d_in, const int* in_sizes, int n_in,
                              void* d_out, int out_size) {
    const float* x   = (const float*)d_in[0];
    const int*   ini = (const int*)  d_in[1];
    const float* hx  = (const float*)d_in[2];
    const float* cx  = (const float*)d_in[3];
    const float* Wih = (const float*)d_in[4];
    const float* Whh = (const float*)d_in[5];
    const float* bih = (const float*)d_in[6];
    const float* bhh = (const float*)d_in[7];
    const float* lnw = (const float*)d_in[8];
    const float* lnb = (const float*)d_in[9];
    float* out = (float*)d_out;

    cudaFuncSetAttribute(lstm_rec, cudaFuncAttributeMaxDynamicSharedMemorySize, SM_TOT);
    init_kernel<<<1, 256>>>();
    cvt_x<<<1024, 256>>>(x, hx);
    lstm_rec<<<NBLK, 256, SM_TOT>>>(ini, cx, Wih, Whh, bih, bhh);
    lstm_epi<<<(BB * TT) / 8, 256>>>(x, lnw, lnb, out);
}